// round 11
// baseline (speedup 1.0000x reference)
#include <cuda_runtime.h>
#include <cuda_fp16.h>
#include <mma.h>
#include <math.h>

using namespace nvcuda;

#define NN 50000
#define EE 1600000
#define HD 128
#define GG 512
#define OD 10
#define KIT 10
#define ALPHA_F 0.1f
#define COEF_A (0.9f / 16.0f)        // per-step rescale by 16
#define FINAL_SCALE 1099511627776.0f // 16^10 = 2^40 (exact)

#define PER_T 49                     // 1024 * 49 = 50176 >= NN

// -------- device scratch (no allocations allowed) --------
__device__ __half g_u0[(size_t)NN * HD];   // ping (scaled x)
__device__ __half g_u1[(size_t)NN * HD];   // pong
__device__ __half g_hh[(size_t)NN * HD];   // teleport term (fp16)
__device__ __half g_Wc16[HD * HD];         // fused W1@W2 (fp16 for wmma)
__device__ float  g_bc[HD];                // fused b1@W2 + b2
__device__ int    g_cnt[NN];               // in-degree histogram
__device__ int    g_rowptr[NN + 1];        // CSR row pointers (by dst)
__device__ int    g_wptr[NN];              // scatter write cursors
__device__ unsigned int g_edges[EE];       // packed: (half w)<<16 | u16 src
__device__ float  g_pool[GG * HD];         // pooled per-graph features

// ---------------------------------------------------------------------------
// Fuse the two linear layers (Wc16 = fp16(W1@W2), bc = b1@W2 + b2) AND zero
// the histogram/pool buffers.
// ---------------------------------------------------------------------------
__global__ void fuse_zero_k(const float* __restrict__ W1, const float* __restrict__ b1,
                            const float* __restrict__ W2, const float* __restrict__ b2) {
    int h = threadIdx.x;
    if (blockIdx.x < HD) {
        int k = blockIdx.x;
        float s = 0.f;
        #pragma unroll 8
        for (int j = 0; j < HD; j++) s = fmaf(W1[k * HD + j], W2[j * HD + h], s);
        g_Wc16[k * HD + h] = __float2half_rn(s);
    } else if (blockIdx.x == HD) {
        float s = b2[h];
        #pragma unroll 8
        for (int j = 0; j < HD; j++) s = fmaf(b1[j], W2[j * HD + h], s);
        g_bc[h] = s;
    } else {
        int i = (blockIdx.x - HD - 1) * 128 + h;
        if (i < NN) g_cnt[i] = 0;
        if (i < GG * HD) g_pool[i] = 0.f;
    }
}

// ---------------------------------------------------------------------------
// x0 = F^T @ Wc + bc via wmma (fp16 in, fp32 accum). Writes g_u0 & g_hh.
// ---------------------------------------------------------------------------
__global__ __launch_bounds__(256) void gemm_x0_wmma_k(const float* __restrict__ F) {
    __shared__ __half sA[16][128];        // F tile (k rows x 128 nodes), fp16
    __shared__ float  sT[8][16][24];      // per-warp epilogue staging
    int n0 = blockIdx.x * 128;
    int tid = threadIdx.x;
    int w = tid >> 5;
    int lane = tid & 31;

    wmma::fragment<wmma::accumulator, 16, 16, 16, float> c[8];
    #pragma unroll
    for (int nt = 0; nt < 8; nt++) wmma::fill_fragment(c[nt], 0.f);

    for (int ks = 0; ks < 8; ks++) {
        #pragma unroll
        for (int i = tid; i < 16 * 128; i += 256) {
            int kk = i >> 7, cc = i & 127;
            int n = n0 + cc;
            float v = (n < NN) ? F[(size_t)(ks * 16 + kk) * NN + n] : 0.f;
            sA[kk][cc] = __float2half_rn(v);
        }
        __syncthreads();
        wmma::fragment<wmma::matrix_a, 16, 16, 16, __half, wmma::col_major> a;
        wmma::load_matrix_sync(a, &sA[0][w * 16], 128);
        #pragma unroll
        for (int nt = 0; nt < 8; nt++) {
            wmma::fragment<wmma::matrix_b, 16, 16, 16, __half, wmma::row_major> b;
            wmma::load_matrix_sync(b, &g_Wc16[(ks * 16) * HD + nt * 16], HD);
            wmma::mma_sync(c[nt], a, b, c[nt]);
        }
        __syncthreads();
    }

    int node_local = lane >> 1;           // 0..15
    int halfsel = lane & 1;               // 0/1 -> dims +0 / +8
    int n = n0 + w * 16 + node_local;
    #pragma unroll
    for (int nt = 0; nt < 8; nt++) {
        wmma::store_matrix_sync(&sT[w][0][0], c[nt], 24, wmma::mem_row_major);
        __syncwarp();
        if (n < NN) {
            int hbase = nt * 16 + halfsel * 8;
            __align__(16) __half hb[8];
            #pragma unroll
            for (int j = 0; j < 8; j++) {
                float v = sT[w][node_local][halfsel * 8 + j] + g_bc[hbase + j];
                hb[j] = __float2half_rn(v);
            }
            uint4 pk = *reinterpret_cast<uint4*>(hb);
            *reinterpret_cast<uint4*>(&g_u0[(size_t)n * HD + hbase]) = pk;
            *reinterpret_cast<uint4*>(&g_hh[(size_t)n * HD + hbase]) = pk;
        }
        __syncwarp();
    }
}

// ---------------------------------------------------------------------------
// In-degree histogram over dst (int4-vectorized; EE % 4 == 0)
// ---------------------------------------------------------------------------
__global__ void hist_k(const int* __restrict__ ei) {
    int t = blockIdx.x * blockDim.x + threadIdx.x;
    int e = t * 4;
    if (e < EE) {
        int4 d = *reinterpret_cast<const int4*>(ei + EE + e);
        atomicAdd(&g_cnt[d.x], 1);
        atomicAdd(&g_cnt[d.y], 1);
        atomicAdd(&g_cnt[d.z], 1);
        atomicAdd(&g_cnt[d.w], 1);
    }
}

// ---------------------------------------------------------------------------
// Single-block exclusive scan of g_cnt -> g_rowptr / g_wptr.
// Thread t owns contiguous counts [t*PER_T, (t+1)*PER_T); two passes:
// (1) per-thread sum, block-scan of 1024 sums; (2) emit with running prefix.
// ---------------------------------------------------------------------------
__device__ __forceinline__ int warp_iscan(int v, int lane) {
    #pragma unroll
    for (int off = 1; off < 32; off <<= 1) {
        int u = __shfl_up_sync(0xffffffffu, v, off);
        if (lane >= off) v += u;
    }
    return v;
}

__global__ __launch_bounds__(1024) void scan_one_k() {
    __shared__ int wsum[32];
    int t = threadIdx.x, lane = t & 31, wid = t >> 5;
    int b = t * PER_T;
    int e = min(b + PER_T, NN);
    int cl[PER_T];
    int s = 0;
    #pragma unroll
    for (int i = 0; i < PER_T; i++) {
        int idx = b + i;
        cl[i] = (idx < NN) ? g_cnt[idx] : 0;
        s += cl[i];
    }
    int v = warp_iscan(s, lane);
    if (lane == 31) wsum[wid] = v;
    __syncthreads();
    if (wid == 0) wsum[lane] = warp_iscan(wsum[lane], lane);
    __syncthreads();
    int run = v - s + (wid ? wsum[wid - 1] : 0);   // exclusive prefix of thread's range
    #pragma unroll
    for (int i = 0; i < PER_T; i++) {
        int idx = b + i;
        if (idx < NN) {
            g_wptr[idx] = run;
            run += cl[i];
            g_rowptr[idx + 1] = run;
        }
    }
    if (t == 0) g_rowptr[0] = 0;
}

// ---------------------------------------------------------------------------
// Scatter edges into CSR order (by dst); 4 edges/thread, vectorized reads
// ---------------------------------------------------------------------------
__global__ void scatter_k(const int* __restrict__ ei, const float* __restrict__ ew) {
    int t = blockIdx.x * blockDim.x + threadIdx.x;
    int e = t * 4;
    if (e < EE) {
        int4  s4 = *reinterpret_cast<const int4*>(ei + e);
        int4  d4 = *reinterpret_cast<const int4*>(ei + EE + e);
        float4 w4 = *reinterpret_cast<const float4*>(ew + e);
        int p;
        p = atomicAdd(&g_wptr[d4.x], 1);
        g_edges[p] = ((unsigned int)__half_as_ushort(__float2half_rn(w4.x)) << 16) | (unsigned int)(s4.x & 0xFFFF);
        p = atomicAdd(&g_wptr[d4.y], 1);
        g_edges[p] = ((unsigned int)__half_as_ushort(__float2half_rn(w4.y)) << 16) | (unsigned int)(s4.y & 0xFFFF);
        p = atomicAdd(&g_wptr[d4.z], 1);
        g_edges[p] = ((unsigned int)__half_as_ushort(__float2half_rn(w4.z)) << 16) | (unsigned int)(s4.z & 0xFFFF);
        p = atomicAdd(&g_wptr[d4.w], 1);
        g_edges[p] = ((unsigned int)__half_as_ushort(__float2half_rn(w4.w)) << 16) | (unsigned int)(s4.w & 0xFFFF);
    }
}

// ---------------------------------------------------------------------------
// One scaled APPNP step (R6 form — best measured):
//   u_out[d] = (0.9/16) * sum_e w_e * u_in[src_e] + (0.1/16^{k+1}) * h[d]
// HALF-WARP per dst node; 4-edge unrolled mainloop.
// ---------------------------------------------------------------------------
__device__ __forceinline__ void edge_fma(unsigned int rec,
                                         const uint4* __restrict__ xin, int sub,
                                         float2& a0, float2& a1, float2& a2, float2& a3) {
    int src = (int)(rec & 0xFFFFu);
    float w = __half2float(__ushort_as_half((unsigned short)(rec >> 16)));
    uint4 raw = xin[src * 16 + sub];
    float2 p0 = __half22float2(*reinterpret_cast<const __half2*>(&raw.x));
    float2 p1 = __half22float2(*reinterpret_cast<const __half2*>(&raw.y));
    float2 p2 = __half22float2(*reinterpret_cast<const __half2*>(&raw.z));
    float2 p3 = __half22float2(*reinterpret_cast<const __half2*>(&raw.w));
    a0.x = fmaf(w, p0.x, a0.x); a0.y = fmaf(w, p0.y, a0.y);
    a1.x = fmaf(w, p1.x, a1.x); a1.y = fmaf(w, p1.y, a1.y);
    a2.x = fmaf(w, p2.x, a2.x); a2.y = fmaf(w, p2.y, a2.y);
    a3.x = fmaf(w, p3.x, a3.x); a3.y = fmaf(w, p3.y, a3.y);
}

__global__ __launch_bounds__(256) void prop_k(int flip, float coefH) {
    const uint4* __restrict__ xin =
        reinterpret_cast<const uint4*>(flip ? g_u1 : g_u0);
    uint4* __restrict__ xout =
        reinterpret_cast<uint4*>(flip ? g_u0 : g_u1);
    int node = (blockIdx.x * blockDim.x + threadIdx.x) >> 4;  // half-warp id
    int sub = threadIdx.x & 15;
    if (node >= NN) return;
    int beg = g_rowptr[node];
    int end = g_rowptr[node + 1];
    float2 a0 = make_float2(0.f, 0.f), a1 = a0, a2 = a0, a3 = a0;

    int j = beg;
    for (; j + 4 <= end; j += 4) {
        unsigned int r0 = g_edges[j + 0];
        unsigned int r1 = g_edges[j + 1];
        unsigned int r2 = g_edges[j + 2];
        unsigned int r3 = g_edges[j + 3];
        int s0 = (int)(r0 & 0xFFFFu), s1 = (int)(r1 & 0xFFFFu);
        int s2 = (int)(r2 & 0xFFFFu), s3 = (int)(r3 & 0xFFFFu);
        uint4 q0 = xin[s0 * 16 + sub];
        uint4 q1 = xin[s1 * 16 + sub];
        uint4 q2 = xin[s2 * 16 + sub];
        uint4 q3 = xin[s3 * 16 + sub];
        float w0 = __half2float(__ushort_as_half((unsigned short)(r0 >> 16)));
        float w1 = __half2float(__ushort_as_half((unsigned short)(r1 >> 16)));
        float w2 = __half2float(__ushort_as_half((unsigned short)(r2 >> 16)));
        float w3 = __half2float(__ushort_as_half((unsigned short)(r3 >> 16)));
        {
            float2 p0 = __half22float2(*reinterpret_cast<const __half2*>(&q0.x));
            float2 p1 = __half22float2(*reinterpret_cast<const __half2*>(&q0.y));
            float2 p2 = __half22float2(*reinterpret_cast<const __half2*>(&q0.z));
            float2 p3 = __half22float2(*reinterpret_cast<const __half2*>(&q0.w));
            a0.x = fmaf(w0, p0.x, a0.x); a0.y = fmaf(w0, p0.y, a0.y);
            a1.x = fmaf(w0, p1.x, a1.x); a1.y = fmaf(w0, p1.y, a1.y);
            a2.x = fmaf(w0, p2.x, a2.x); a2.y = fmaf(w0, p2.y, a2.y);
            a3.x = fmaf(w0, p3.x, a3.x); a3.y = fmaf(w0, p3.y, a3.y);
        }
        {
            float2 p0 = __half22float2(*reinterpret_cast<const __half2*>(&q1.x));
            float2 p1 = __half22float2(*reinterpret_cast<const __half2*>(&q1.y));
            float2 p2 = __half22float2(*reinterpret_cast<const __half2*>(&q1.z));
            float2 p3 = __half22float2(*reinterpret_cast<const __half2*>(&q1.w));
            a0.x = fmaf(w1, p0.x, a0.x); a0.y = fmaf(w1, p0.y, a0.y);
            a1.x = fmaf(w1, p1.x, a1.x); a1.y = fmaf(w1, p1.y, a1.y);
            a2.x = fmaf(w1, p2.x, a2.x); a2.y = fmaf(w1, p2.y, a2.y);
            a3.x = fmaf(w1, p3.x, a3.x); a3.y = fmaf(w1, p3.y, a3.y);
        }
        {
            float2 p0 = __half22float2(*reinterpret_cast<const __half2*>(&q2.x));
            float2 p1 = __half22float2(*reinterpret_cast<const __half2*>(&q2.y));
            float2 p2 = __half22float2(*reinterpret_cast<const __half2*>(&q2.z));
            float2 p3 = __half22float2(*reinterpret_cast<const __half2*>(&q2.w));
            a0.x = fmaf(w2, p0.x, a0.x); a0.y = fmaf(w2, p0.y, a0.y);
            a1.x = fmaf(w2, p1.x, a1.x); a1.y = fmaf(w2, p1.y, a1.y);
            a2.x = fmaf(w2, p2.x, a2.x); a2.y = fmaf(w2, p2.y, a2.y);
            a3.x = fmaf(w2, p3.x, a3.x); a3.y = fmaf(w2, p3.y, a3.y);
        }
        {
            float2 p0 = __half22float2(*reinterpret_cast<const __half2*>(&q3.x));
            float2 p1 = __half22float2(*reinterpret_cast<const __half2*>(&q3.y));
            float2 p2 = __half22float2(*reinterpret_cast<const __half2*>(&q3.z));
            float2 p3 = __half22float2(*reinterpret_cast<const __half2*>(&q3.w));
            a0.x = fmaf(w3, p0.x, a0.x); a0.y = fmaf(w3, p0.y, a0.y);
            a1.x = fmaf(w3, p1.x, a1.x); a1.y = fmaf(w3, p1.y, a1.y);
            a2.x = fmaf(w3, p2.x, a2.x); a2.y = fmaf(w3, p2.y, a2.y);
            a3.x = fmaf(w3, p3.x, a3.x); a3.y = fmaf(w3, p3.y, a3.y);
        }
    }
    #pragma unroll 1
    for (; j < end; j++)
        edge_fma(g_edges[j], xin, sub, a0, a1, a2, a3);

    uint4 hraw = reinterpret_cast<const uint4*>(g_hh)[node * 16 + sub];
    float2 h0 = __half22float2(*reinterpret_cast<const __half2*>(&hraw.x));
    float2 h1 = __half22float2(*reinterpret_cast<const __half2*>(&hraw.y));
    float2 h2 = __half22float2(*reinterpret_cast<const __half2*>(&hraw.z));
    float2 h3 = __half22float2(*reinterpret_cast<const __half2*>(&hraw.w));
    float2 o0, o1, o2, o3;
    o0.x = fmaf(COEF_A, a0.x, coefH * h0.x); o0.y = fmaf(COEF_A, a0.y, coefH * h0.y);
    o1.x = fmaf(COEF_A, a1.x, coefH * h1.x); o1.y = fmaf(COEF_A, a1.y, coefH * h1.y);
    o2.x = fmaf(COEF_A, a2.x, coefH * h2.x); o2.y = fmaf(COEF_A, a2.y, coefH * h2.y);
    o3.x = fmaf(COEF_A, a3.x, coefH * h3.x); o3.y = fmaf(COEF_A, a3.y, coefH * h3.y);
    uint4 outw;
    *reinterpret_cast<__half2*>(&outw.x) = __float22half2_rn(o0);
    *reinterpret_cast<__half2*>(&outw.y) = __float22half2_rn(o1);
    *reinterpret_cast<__half2*>(&outw.z) = __float22half2_rn(o2);
    *reinterpret_cast<__half2*>(&outw.w) = __float22half2_rn(o3);
    xout[node * 16 + sub] = outw;
}

// ---------------------------------------------------------------------------
// Segment-sum pooling over sorted batch (reads final u from g_u0, unscales
// by 16^10 = 2^40).
// ---------------------------------------------------------------------------
__device__ __forceinline__ void pool_flush(int g, float4 acc, int lane) {
    float* p = g_pool + (size_t)g * HD + lane * 4;
    atomicAdd(p + 0, acc.x * FINAL_SCALE);
    atomicAdd(p + 1, acc.y * FINAL_SCALE);
    atomicAdd(p + 2, acc.z * FINAL_SCALE);
    atomicAdd(p + 3, acc.w * FINAL_SCALE);
}

__global__ __launch_bounds__(256) void pool_k(const int* __restrict__ batch) {
    int warp_id = (blockIdx.x * blockDim.x + threadIdx.x) >> 5;
    int lane = threadIdx.x & 31;
    int n0 = warp_id * 64;
    if (n0 >= NN) return;
    int n1 = min(n0 + 64, NN);
    float4 acc = make_float4(0.f, 0.f, 0.f, 0.f);
    int curg = batch[n0];
    for (int n = n0; n < n1; n++) {
        int g = batch[n];
        if (g != curg) {
            pool_flush(curg, acc, lane);
            acc = make_float4(0.f, 0.f, 0.f, 0.f);
            curg = g;
        }
        uint2 raw = *reinterpret_cast<const uint2*>(g_u0 + (size_t)n * HD + lane * 4);
        float2 fa = __half22float2(*reinterpret_cast<const __half2*>(&raw.x));
        float2 fb = __half22float2(*reinterpret_cast<const __half2*>(&raw.y));
        acc.x += fa.x; acc.y += fa.y; acc.z += fb.x; acc.w += fb.y;
    }
    pool_flush(curg, acc, lane);
}

// ---------------------------------------------------------------------------
// Head: y = relu(pool @ V0w + V0b) @ V1w + V1b; out = log_softmax(y)
// ---------------------------------------------------------------------------
__global__ __launch_bounds__(128) void head_k(const float* __restrict__ V0w,
                                              const float* __restrict__ V0b,
                                              const float* __restrict__ V1w,
                                              const float* __restrict__ V1b,
                                              float* __restrict__ out) {
    __shared__ float sp[HD];
    __shared__ float sz[HD];
    __shared__ float sy[OD];
    int g = blockIdx.x;
    int t = threadIdx.x;
    sp[t] = g_pool[(size_t)g * HD + t];
    __syncthreads();
    float s = V0b[t];
    #pragma unroll 8
    for (int k = 0; k < HD; k++) s = fmaf(sp[k], V0w[k * HD + t], s);
    sz[t] = fmaxf(s, 0.f);
    __syncthreads();
    if (t < OD) {
        float y = V1b[t];
        #pragma unroll 8
        for (int h = 0; h < HD; h++) y = fmaf(sz[h], V1w[h * OD + t], y);
        sy[t] = y;
    }
    __syncthreads();
    if (t == 0) {
        float m = -INFINITY;
        #pragma unroll
        for (int o = 0; o < OD; o++) m = fmaxf(m, sy[o]);
        float sum = 0.f;
        #pragma unroll
        for (int o = 0; o < OD; o++) sum += expf(sy[o] - m);
        float lse = m + logf(sum);
        #pragma unroll
        for (int o = 0; o < OD; o++) out[g * OD + o] = sy[o] - lse;
    }
}

// ---------------------------------------------------------------------------
extern "C" void kernel_launch(void* const* d_in, const int* in_sizes, int n_in,
                              void* d_out, int out_size) {
    const float* features    = (const float*)d_in[0];
    const float* edge_weight = (const float*)d_in[1];
    const float* W1  = (const float*)d_in[2];
    const float* b1  = (const float*)d_in[3];
    const float* W2  = (const float*)d_in[4];
    const float* b2  = (const float*)d_in[5];
    const float* V0w = (const float*)d_in[6];
    const float* V0b = (const float*)d_in[7];
    const float* V1w = (const float*)d_in[8];
    const float* V1b = (const float*)d_in[9];
    const int* edge_index = (const int*)d_in[10];
    const int* batch      = (const int*)d_in[11];
    float* out = (float*)d_out;

    // MLP-weight fusion + buffer zeroing, then wmma node GEMM
    int zero_blocks = (GG * HD + 127) / 128;
    fuse_zero_k<<<HD + 1 + zero_blocks, HD>>>(W1, b1, W2, b2);
    gemm_x0_wmma_k<<<(NN + 127) / 128, 256>>>(features);

    // CSR build (by dst) — hist, single-block scan, scatter
    hist_k<<<(EE / 4 + 255) / 256, 256>>>(edge_index);
    scan_one_k<<<1, 1024>>>();
    scatter_k<<<(EE / 4 + 255) / 256, 256>>>(edge_index, edge_weight);

    // APPNP propagation, K=10 (scaled fp16; ends in g_u0)
    int prop_blocks = (NN * 16 + 255) / 256;
    float cscale = 1.0f;   // 1/16^{it}
    for (int it = 0; it < KIT; it++) {
        cscale *= 0.0625f;                    // 1/16^{it+1}
        float coefH = ALPHA_F * cscale;
        prop_k<<<prop_blocks, 256>>>(it & 1, coefH);
    }

    // Pool + head
    int pool_warps = (NN + 63) / 64;
    pool_k<<<(pool_warps * 32 + 255) / 256, 256>>>(batch);
    head_k<<<GG, HD>>>(V0w, V0b, V1w, V1b, out);
}

// round 13
// speedup vs baseline: 1.1068x; 1.1068x over previous
#include <cuda_runtime.h>
#include <cuda_fp16.h>
#include <mma.h>
#include <math.h>

using namespace nvcuda;

#define NN 50000
#define EE 1600000
#define HD 128
#define GG 512
#define OD 10
#define KIT 10
#define ALPHA_F 0.1f
#define COEF_A (0.9f / 16.0f)        // per-step rescale by 16
#define FINAL_SCALE 1099511627776.0f // 16^10 = 2^40 (exact)

#define SCAN_B 1024
#define SCAN_NBLK ((NN + SCAN_B - 1) / SCAN_B)   // 49

// -------- device scratch (no allocations allowed) --------
__device__ __half g_u0[(size_t)NN * HD];   // ping (scaled x)
__device__ __half g_u1[(size_t)NN * HD];   // pong
__device__ __half g_hh[(size_t)NN * HD];   // teleport term (fp16)
__device__ __half g_Wc16[HD * HD];         // fused W1@W2 (fp16 for wmma)
__device__ float  g_bc[HD];                // fused b1@W2 + b2
__device__ int    g_cnt[NN];               // in-degree histogram
__device__ int    g_rowptr[NN + 1];        // CSR row pointers (by dst)
__device__ int    g_wptr[NN];              // scatter write cursors
__device__ unsigned int g_edges[EE];       // packed: (half w)<<16 | u16 src
__device__ float  g_pool[GG * HD];         // pooled per-graph features

// ---------------------------------------------------------------------------
// Fuse the two linear layers (Wc16 = fp16(W1@W2), bc = b1@W2 + b2) AND zero
// the histogram/pool buffers.
// ---------------------------------------------------------------------------
__global__ void fuse_zero_k(const float* __restrict__ W1, const float* __restrict__ b1,
                            const float* __restrict__ W2, const float* __restrict__ b2) {
    int h = threadIdx.x;
    if (blockIdx.x < HD) {
        int k = blockIdx.x;
        float s = 0.f;
        #pragma unroll 8
        for (int j = 0; j < HD; j++) s = fmaf(W1[k * HD + j], W2[j * HD + h], s);
        g_Wc16[k * HD + h] = __float2half_rn(s);
    } else if (blockIdx.x == HD) {
        float s = b2[h];
        #pragma unroll 8
        for (int j = 0; j < HD; j++) s = fmaf(b1[j], W2[j * HD + h], s);
        g_bc[h] = s;
    } else {
        int i = (blockIdx.x - HD - 1) * 128 + h;
        if (i < NN) g_cnt[i] = 0;
        if (i < GG * HD) g_pool[i] = 0.f;
    }
}

// ---------------------------------------------------------------------------
// x0 = F^T @ Wc + bc via wmma (fp16 in, fp32 accum). Writes g_u0 & g_hh.
// ---------------------------------------------------------------------------
__global__ __launch_bounds__(256) void gemm_x0_wmma_k(const float* __restrict__ F) {
    __shared__ __half sA[16][128];        // F tile (k rows x 128 nodes), fp16
    __shared__ float  sT[8][16][24];      // per-warp epilogue staging
    int n0 = blockIdx.x * 128;
    int tid = threadIdx.x;
    int w = tid >> 5;
    int lane = tid & 31;

    wmma::fragment<wmma::accumulator, 16, 16, 16, float> c[8];
    #pragma unroll
    for (int nt = 0; nt < 8; nt++) wmma::fill_fragment(c[nt], 0.f);

    for (int ks = 0; ks < 8; ks++) {
        #pragma unroll
        for (int i = tid; i < 16 * 128; i += 256) {
            int kk = i >> 7, cc = i & 127;
            int n = n0 + cc;
            float v = (n < NN) ? F[(size_t)(ks * 16 + kk) * NN + n] : 0.f;
            sA[kk][cc] = __float2half_rn(v);
        }
        __syncthreads();
        wmma::fragment<wmma::matrix_a, 16, 16, 16, __half, wmma::col_major> a;
        wmma::load_matrix_sync(a, &sA[0][w * 16], 128);
        #pragma unroll
        for (int nt = 0; nt < 8; nt++) {
            wmma::fragment<wmma::matrix_b, 16, 16, 16, __half, wmma::row_major> b;
            wmma::load_matrix_sync(b, &g_Wc16[(ks * 16) * HD + nt * 16], HD);
            wmma::mma_sync(c[nt], a, b, c[nt]);
        }
        __syncthreads();
    }

    int node_local = lane >> 1;           // 0..15
    int halfsel = lane & 1;               // 0/1 -> dims +0 / +8
    int n = n0 + w * 16 + node_local;
    #pragma unroll
    for (int nt = 0; nt < 8; nt++) {
        wmma::store_matrix_sync(&sT[w][0][0], c[nt], 24, wmma::mem_row_major);
        __syncwarp();
        if (n < NN) {
            int hbase = nt * 16 + halfsel * 8;
            __align__(16) __half hb[8];
            #pragma unroll
            for (int j = 0; j < 8; j++) {
                float v = sT[w][node_local][halfsel * 8 + j] + g_bc[hbase + j];
                hb[j] = __float2half_rn(v);
            }
            uint4 pk = *reinterpret_cast<uint4*>(hb);
            *reinterpret_cast<uint4*>(&g_u0[(size_t)n * HD + hbase]) = pk;
            *reinterpret_cast<uint4*>(&g_hh[(size_t)n * HD + hbase]) = pk;
        }
        __syncwarp();
    }
}

// ---------------------------------------------------------------------------
// In-degree histogram over dst (int4-vectorized; EE % 4 == 0)
// ---------------------------------------------------------------------------
__global__ void hist_k(const int* __restrict__ ei) {
    int t = blockIdx.x * blockDim.x + threadIdx.x;
    int e = t * 4;
    if (e < EE) {
        int4 d = *reinterpret_cast<const int4*>(ei + EE + e);
        atomicAdd(&g_cnt[d.x], 1);
        atomicAdd(&g_cnt[d.y], 1);
        atomicAdd(&g_cnt[d.z], 1);
        atomicAdd(&g_cnt[d.w], 1);
    }
}

// ---------------------------------------------------------------------------
// ONE-launch exclusive scan: block b redundantly sums counts [0, b*1024)
// (coalesced, parallel across 1024 threads) for its global offset, then does
// the standard in-register warp scan of its own 1024-chunk. No spills, no
// per-thread arrays, no inter-block sync.
// ---------------------------------------------------------------------------
__device__ __forceinline__ int warp_iscan(int v, int lane) {
    #pragma unroll
    for (int off = 1; off < 32; off <<= 1) {
        int u = __shfl_up_sync(0xffffffffu, v, off);
        if (lane >= off) v += u;
    }
    return v;
}

__global__ __launch_bounds__(SCAN_B) void scan_k() {
    __shared__ int wsum[32];
    __shared__ int sboff;
    int t = threadIdx.x, lane = t & 31, wid = t >> 5;

    // ---- block offset: sum of all counts before this block's chunk ----
    int limit = blockIdx.x * SCAN_B;
    int acc = 0;
    for (int i = t; i < limit; i += SCAN_B) acc += g_cnt[i];
    #pragma unroll
    for (int off = 16; off > 0; off >>= 1)
        acc += __shfl_down_sync(0xffffffffu, acc, off);
    if (lane == 0) wsum[wid] = acc;
    __syncthreads();
    if (wid == 0) {
        int v = wsum[lane];
        #pragma unroll
        for (int off = 16; off > 0; off >>= 1)
            v += __shfl_down_sync(0xffffffffu, v, off);
        if (lane == 0) sboff = v;
    }
    __syncthreads();
    int boff = sboff;

    // ---- scan own chunk ----
    int idx = blockIdx.x * SCAN_B + t;
    int c = (idx < NN) ? g_cnt[idx] : 0;
    int v = warp_iscan(c, lane);
    if (lane == 31) wsum[wid] = v;
    __syncthreads();
    if (wid == 0) wsum[lane] = warp_iscan(wsum[lane], lane);
    __syncthreads();
    int incl = v + (wid ? wsum[wid - 1] : 0) + boff;
    if (idx < NN) {
        g_rowptr[idx + 1] = incl;
        g_wptr[idx]       = incl - c;
    }
    if (idx == 0) g_rowptr[0] = 0;
}

// ---------------------------------------------------------------------------
// Scatter edges into CSR order (by dst); 4 edges/thread, vectorized reads
// ---------------------------------------------------------------------------
__global__ void scatter_k(const int* __restrict__ ei, const float* __restrict__ ew) {
    int t = blockIdx.x * blockDim.x + threadIdx.x;
    int e = t * 4;
    if (e < EE) {
        int4  s4 = *reinterpret_cast<const int4*>(ei + e);
        int4  d4 = *reinterpret_cast<const int4*>(ei + EE + e);
        float4 w4 = *reinterpret_cast<const float4*>(ew + e);
        int p;
        p = atomicAdd(&g_wptr[d4.x], 1);
        g_edges[p] = ((unsigned int)__half_as_ushort(__float2half_rn(w4.x)) << 16) | (unsigned int)(s4.x & 0xFFFF);
        p = atomicAdd(&g_wptr[d4.y], 1);
        g_edges[p] = ((unsigned int)__half_as_ushort(__float2half_rn(w4.y)) << 16) | (unsigned int)(s4.y & 0xFFFF);
        p = atomicAdd(&g_wptr[d4.z], 1);
        g_edges[p] = ((unsigned int)__half_as_ushort(__float2half_rn(w4.z)) << 16) | (unsigned int)(s4.z & 0xFFFF);
        p = atomicAdd(&g_wptr[d4.w], 1);
        g_edges[p] = ((unsigned int)__half_as_ushort(__float2half_rn(w4.w)) << 16) | (unsigned int)(s4.w & 0xFFFF);
    }
}

// ---------------------------------------------------------------------------
// One scaled APPNP step (R6 form — best measured):
//   u_out[d] = (0.9/16) * sum_e w_e * u_in[src_e] + (0.1/16^{k+1}) * h[d]
// HALF-WARP per dst node; 4-edge unrolled mainloop.
// ---------------------------------------------------------------------------
__device__ __forceinline__ void edge_fma(unsigned int rec,
                                         const uint4* __restrict__ xin, int sub,
                                         float2& a0, float2& a1, float2& a2, float2& a3) {
    int src = (int)(rec & 0xFFFFu);
    float w = __half2float(__ushort_as_half((unsigned short)(rec >> 16)));
    uint4 raw = xin[src * 16 + sub];
    float2 p0 = __half22float2(*reinterpret_cast<const __half2*>(&raw.x));
    float2 p1 = __half22float2(*reinterpret_cast<const __half2*>(&raw.y));
    float2 p2 = __half22float2(*reinterpret_cast<const __half2*>(&raw.z));
    float2 p3 = __half22float2(*reinterpret_cast<const __half2*>(&raw.w));
    a0.x = fmaf(w, p0.x, a0.x); a0.y = fmaf(w, p0.y, a0.y);
    a1.x = fmaf(w, p1.x, a1.x); a1.y = fmaf(w, p1.y, a1.y);
    a2.x = fmaf(w, p2.x, a2.x); a2.y = fmaf(w, p2.y, a2.y);
    a3.x = fmaf(w, p3.x, a3.x); a3.y = fmaf(w, p3.y, a3.y);
}

__global__ __launch_bounds__(256) void prop_k(int flip, float coefH) {
    const uint4* __restrict__ xin =
        reinterpret_cast<const uint4*>(flip ? g_u1 : g_u0);
    uint4* __restrict__ xout =
        reinterpret_cast<uint4*>(flip ? g_u0 : g_u1);
    int node = (blockIdx.x * blockDim.x + threadIdx.x) >> 4;  // half-warp id
    int sub = threadIdx.x & 15;
    if (node >= NN) return;
    int beg = g_rowptr[node];
    int end = g_rowptr[node + 1];
    float2 a0 = make_float2(0.f, 0.f), a1 = a0, a2 = a0, a3 = a0;

    int j = beg;
    for (; j + 4 <= end; j += 4) {
        unsigned int r0 = g_edges[j + 0];
        unsigned int r1 = g_edges[j + 1];
        unsigned int r2 = g_edges[j + 2];
        unsigned int r3 = g_edges[j + 3];
        int s0 = (int)(r0 & 0xFFFFu), s1 = (int)(r1 & 0xFFFFu);
        int s2 = (int)(r2 & 0xFFFFu), s3 = (int)(r3 & 0xFFFFu);
        uint4 q0 = xin[s0 * 16 + sub];
        uint4 q1 = xin[s1 * 16 + sub];
        uint4 q2 = xin[s2 * 16 + sub];
        uint4 q3 = xin[s3 * 16 + sub];
        float w0 = __half2float(__ushort_as_half((unsigned short)(r0 >> 16)));
        float w1 = __half2float(__ushort_as_half((unsigned short)(r1 >> 16)));
        float w2 = __half2float(__ushort_as_half((unsigned short)(r2 >> 16)));
        float w3 = __half2float(__ushort_as_half((unsigned short)(r3 >> 16)));
        {
            float2 p0 = __half22float2(*reinterpret_cast<const __half2*>(&q0.x));
            float2 p1 = __half22float2(*reinterpret_cast<const __half2*>(&q0.y));
            float2 p2 = __half22float2(*reinterpret_cast<const __half2*>(&q0.z));
            float2 p3 = __half22float2(*reinterpret_cast<const __half2*>(&q0.w));
            a0.x = fmaf(w0, p0.x, a0.x); a0.y = fmaf(w0, p0.y, a0.y);
            a1.x = fmaf(w0, p1.x, a1.x); a1.y = fmaf(w0, p1.y, a1.y);
            a2.x = fmaf(w0, p2.x, a2.x); a2.y = fmaf(w0, p2.y, a2.y);
            a3.x = fmaf(w0, p3.x, a3.x); a3.y = fmaf(w0, p3.y, a3.y);
        }
        {
            float2 p0 = __half22float2(*reinterpret_cast<const __half2*>(&q1.x));
            float2 p1 = __half22float2(*reinterpret_cast<const __half2*>(&q1.y));
            float2 p2 = __half22float2(*reinterpret_cast<const __half2*>(&q1.z));
            float2 p3 = __half22float2(*reinterpret_cast<const __half2*>(&q1.w));
            a0.x = fmaf(w1, p0.x, a0.x); a0.y = fmaf(w1, p0.y, a0.y);
            a1.x = fmaf(w1, p1.x, a1.x); a1.y = fmaf(w1, p1.y, a1.y);
            a2.x = fmaf(w1, p2.x, a2.x); a2.y = fmaf(w1, p2.y, a2.y);
            a3.x = fmaf(w1, p3.x, a3.x); a3.y = fmaf(w1, p3.y, a3.y);
        }
        {
            float2 p0 = __half22float2(*reinterpret_cast<const __half2*>(&q2.x));
            float2 p1 = __half22float2(*reinterpret_cast<const __half2*>(&q2.y));
            float2 p2 = __half22float2(*reinterpret_cast<const __half2*>(&q2.z));
            float2 p3 = __half22float2(*reinterpret_cast<const __half2*>(&q2.w));
            a0.x = fmaf(w2, p0.x, a0.x); a0.y = fmaf(w2, p0.y, a0.y);
            a1.x = fmaf(w2, p1.x, a1.x); a1.y = fmaf(w2, p1.y, a1.y);
            a2.x = fmaf(w2, p2.x, a2.x); a2.y = fmaf(w2, p2.y, a2.y);
            a3.x = fmaf(w2, p3.x, a3.x); a3.y = fmaf(w2, p3.y, a3.y);
        }
        {
            float2 p0 = __half22float2(*reinterpret_cast<const __half2*>(&q3.x));
            float2 p1 = __half22float2(*reinterpret_cast<const __half2*>(&q3.y));
            float2 p2 = __half22float2(*reinterpret_cast<const __half2*>(&q3.z));
            float2 p3 = __half22float2(*reinterpret_cast<const __half2*>(&q3.w));
            a0.x = fmaf(w3, p0.x, a0.x); a0.y = fmaf(w3, p0.y, a0.y);
            a1.x = fmaf(w3, p1.x, a1.x); a1.y = fmaf(w3, p1.y, a1.y);
            a2.x = fmaf(w3, p2.x, a2.x); a2.y = fmaf(w3, p2.y, a2.y);
            a3.x = fmaf(w3, p3.x, a3.x); a3.y = fmaf(w3, p3.y, a3.y);
        }
    }
    #pragma unroll 1
    for (; j < end; j++)
        edge_fma(g_edges[j], xin, sub, a0, a1, a2, a3);

    uint4 hraw = reinterpret_cast<const uint4*>(g_hh)[node * 16 + sub];
    float2 h0 = __half22float2(*reinterpret_cast<const __half2*>(&hraw.x));
    float2 h1 = __half22float2(*reinterpret_cast<const __half2*>(&hraw.y));
    float2 h2 = __half22float2(*reinterpret_cast<const __half2*>(&hraw.z));
    float2 h3 = __half22float2(*reinterpret_cast<const __half2*>(&hraw.w));
    float2 o0, o1, o2, o3;
    o0.x = fmaf(COEF_A, a0.x, coefH * h0.x); o0.y = fmaf(COEF_A, a0.y, coefH * h0.y);
    o1.x = fmaf(COEF_A, a1.x, coefH * h1.x); o1.y = fmaf(COEF_A, a1.y, coefH * h1.y);
    o2.x = fmaf(COEF_A, a2.x, coefH * h2.x); o2.y = fmaf(COEF_A, a2.y, coefH * h2.y);
    o3.x = fmaf(COEF_A, a3.x, coefH * h3.x); o3.y = fmaf(COEF_A, a3.y, coefH * h3.y);
    uint4 outw;
    *reinterpret_cast<__half2*>(&outw.x) = __float22half2_rn(o0);
    *reinterpret_cast<__half2*>(&outw.y) = __float22half2_rn(o1);
    *reinterpret_cast<__half2*>(&outw.z) = __float22half2_rn(o2);
    *reinterpret_cast<__half2*>(&outw.w) = __float22half2_rn(o3);
    xout[node * 16 + sub] = outw;
}

// ---------------------------------------------------------------------------
// Segment-sum pooling over sorted batch (reads final u from g_u0, unscales
// by 16^10 = 2^40).
// ---------------------------------------------------------------------------
__device__ __forceinline__ void pool_flush(int g, float4 acc, int lane) {
    float* p = g_pool + (size_t)g * HD + lane * 4;
    atomicAdd(p + 0, acc.x * FINAL_SCALE);
    atomicAdd(p + 1, acc.y * FINAL_SCALE);
    atomicAdd(p + 2, acc.z * FINAL_SCALE);
    atomicAdd(p + 3, acc.w * FINAL_SCALE);
}

__global__ __launch_bounds__(256) void pool_k(const int* __restrict__ batch) {
    int warp_id = (blockIdx.x * blockDim.x + threadIdx.x) >> 5;
    int lane = threadIdx.x & 31;
    int n0 = warp_id * 64;
    if (n0 >= NN) return;
    int n1 = min(n0 + 64, NN);
    float4 acc = make_float4(0.f, 0.f, 0.f, 0.f);
    int curg = batch[n0];
    for (int n = n0; n < n1; n++) {
        int g = batch[n];
        if (g != curg) {
            pool_flush(curg, acc, lane);
            acc = make_float4(0.f, 0.f, 0.f, 0.f);
            curg = g;
        }
        uint2 raw = *reinterpret_cast<const uint2*>(g_u0 + (size_t)n * HD + lane * 4);
        float2 fa = __half22float2(*reinterpret_cast<const __half2*>(&raw.x));
        float2 fb = __half22float2(*reinterpret_cast<const __half2*>(&raw.y));
        acc.x += fa.x; acc.y += fa.y; acc.z += fb.x; acc.w += fb.y;
    }
    pool_flush(curg, acc, lane);
}

// ---------------------------------------------------------------------------
// Head: y = relu(pool @ V0w + V0b) @ V1w + V1b; out = log_softmax(y)
// ---------------------------------------------------------------------------
__global__ __launch_bounds__(128) void head_k(const float* __restrict__ V0w,
                                              const float* __restrict__ V0b,
                                              const float* __restrict__ V1w,
                                              const float* __restrict__ V1b,
                                              float* __restrict__ out) {
    __shared__ float sp[HD];
    __shared__ float sz[HD];
    __shared__ float sy[OD];
    int g = blockIdx.x;
    int t = threadIdx.x;
    sp[t] = g_pool[(size_t)g * HD + t];
    __syncthreads();
    float s = V0b[t];
    #pragma unroll 8
    for (int k = 0; k < HD; k++) s = fmaf(sp[k], V0w[k * HD + t], s);
    sz[t] = fmaxf(s, 0.f);
    __syncthreads();
    if (t < OD) {
        float y = V1b[t];
        #pragma unroll 8
        for (int h = 0; h < HD; h++) y = fmaf(sz[h], V1w[h * OD + t], y);
        sy[t] = y;
    }
    __syncthreads();
    if (t == 0) {
        float m = -INFINITY;
        #pragma unroll
        for (int o = 0; o < OD; o++) m = fmaxf(m, sy[o]);
        float sum = 0.f;
        #pragma unroll
        for (int o = 0; o < OD; o++) sum += expf(sy[o] - m);
        float lse = m + logf(sum);
        #pragma unroll
        for (int o = 0; o < OD; o++) out[g * OD + o] = sy[o] - lse;
    }
}

// ---------------------------------------------------------------------------
extern "C" void kernel_launch(void* const* d_in, const int* in_sizes, int n_in,
                              void* d_out, int out_size) {
    const float* features    = (const float*)d_in[0];
    const float* edge_weight = (const float*)d_in[1];
    const float* W1  = (const float*)d_in[2];
    const float* b1  = (const float*)d_in[3];
    const float* W2  = (const float*)d_in[4];
    const float* b2  = (const float*)d_in[5];
    const float* V0w = (const float*)d_in[6];
    const float* V0b = (const float*)d_in[7];
    const float* V1w = (const float*)d_in[8];
    const float* V1b = (const float*)d_in[9];
    const int* edge_index = (const int*)d_in[10];
    const int* batch      = (const int*)d_in[11];
    float* out = (float*)d_out;

    // MLP-weight fusion + buffer zeroing, then wmma node GEMM
    int zero_blocks = (GG * HD + 127) / 128;
    fuse_zero_k<<<HD + 1 + zero_blocks, HD>>>(W1, b1, W2, b2);
    gemm_x0_wmma_k<<<(NN + 127) / 128, 256>>>(features);

    // CSR build (by dst) — hist, one-launch scan, scatter
    hist_k<<<(EE / 4 + 255) / 256, 256>>>(edge_index);
    scan_k<<<SCAN_NBLK, SCAN_B>>>();
    scatter_k<<<(EE / 4 + 255) / 256, 256>>>(edge_index, edge_weight);

    // APPNP propagation, K=10 (scaled fp16; ends in g_u0)
    int prop_blocks = (NN * 16 + 255) / 256;
    float cscale = 1.0f;   // 1/16^{it}
    for (int it = 0; it < KIT; it++) {
        cscale *= 0.0625f;                    // 1/16^{it+1}
        float coefH = ALPHA_F * cscale;
        prop_k<<<prop_blocks, 256>>>(it & 1, coefH);
    }

    // Pool + head
    int pool_warps = (NN + 63) / 64;
    pool_k<<<(pool_warps * 32 + 255) / 256, 256>>>(batch);
    head_k<<<GG, HD>>>(V0w, V0b, V1w, V1b, out);
}

// round 14
// speedup vs baseline: 1.1486x; 1.0377x over previous
#include <cuda_runtime.h>
#include <cuda_fp16.h>
#include <mma.h>
#include <math.h>

using namespace nvcuda;

#define NN 50000
#define EE 1600000
#define HD 128
#define GG 512
#define OD 10
#define KIT 10
#define ALPHA_F 0.1f
#define COEF_A (0.9f / 16.0f)        // per-step rescale by 16
#define FINAL_SCALE 1099511627776.0f // 16^10 = 2^40 (exact)

#define SCAN_B 1024
#define SCAN_NBLK ((NN + SCAN_B - 1) / SCAN_B)   // 49

// -------- device scratch (no allocations allowed) --------
__device__ __half g_u0[(size_t)NN * HD];   // ping (scaled x)
__device__ __half g_u1[(size_t)NN * HD];   // pong
__device__ __half g_hh[(size_t)NN * HD];   // teleport term (fp16)
__device__ __half g_Wc16[HD * HD];         // fused W1@W2 (fp16 for wmma)
__device__ float  g_bc[HD];                // fused b1@W2 + b2
__device__ int    g_cnt[NN];               // in-degree histogram
__device__ int    g_rowptr[NN + 1];        // CSR row pointers (by dst)
__device__ int    g_wptr[NN];              // scatter write cursors
__device__ unsigned int g_edges[EE];       // packed: (half w)<<16 | u16 src

// ---------------------------------------------------------------------------
// Fuse the two linear layers (Wc16 = fp16(W1@W2), bc = b1@W2 + b2) AND zero
// the histogram.
// ---------------------------------------------------------------------------
__global__ void fuse_zero_k(const float* __restrict__ W1, const float* __restrict__ b1,
                            const float* __restrict__ W2, const float* __restrict__ b2) {
    int h = threadIdx.x;
    if (blockIdx.x < HD) {
        int k = blockIdx.x;
        float s = 0.f;
        #pragma unroll 8
        for (int j = 0; j < HD; j++) s = fmaf(W1[k * HD + j], W2[j * HD + h], s);
        g_Wc16[k * HD + h] = __float2half_rn(s);
    } else if (blockIdx.x == HD) {
        float s = b2[h];
        #pragma unroll 8
        for (int j = 0; j < HD; j++) s = fmaf(b1[j], W2[j * HD + h], s);
        g_bc[h] = s;
    } else {
        int i = (blockIdx.x - HD - 1) * 128 + h;
        if (i < NN) g_cnt[i] = 0;
    }
}

// ---------------------------------------------------------------------------
// x0 = F^T @ Wc + bc via wmma (fp16 in, fp32 accum). Writes g_u0 & g_hh.
// ---------------------------------------------------------------------------
__global__ __launch_bounds__(256) void gemm_x0_wmma_k(const float* __restrict__ F) {
    __shared__ __half sA[16][128];        // F tile (k rows x 128 nodes), fp16
    __shared__ float  sT[8][16][24];      // per-warp epilogue staging
    int n0 = blockIdx.x * 128;
    int tid = threadIdx.x;
    int w = tid >> 5;
    int lane = tid & 31;

    wmma::fragment<wmma::accumulator, 16, 16, 16, float> c[8];
    #pragma unroll
    for (int nt = 0; nt < 8; nt++) wmma::fill_fragment(c[nt], 0.f);

    for (int ks = 0; ks < 8; ks++) {
        #pragma unroll
        for (int i = tid; i < 16 * 128; i += 256) {
            int kk = i >> 7, cc = i & 127;
            int n = n0 + cc;
            float v = (n < NN) ? F[(size_t)(ks * 16 + kk) * NN + n] : 0.f;
            sA[kk][cc] = __float2half_rn(v);
        }
        __syncthreads();
        wmma::fragment<wmma::matrix_a, 16, 16, 16, __half, wmma::col_major> a;
        wmma::load_matrix_sync(a, &sA[0][w * 16], 128);
        #pragma unroll
        for (int nt = 0; nt < 8; nt++) {
            wmma::fragment<wmma::matrix_b, 16, 16, 16, __half, wmma::row_major> b;
            wmma::load_matrix_sync(b, &g_Wc16[(ks * 16) * HD + nt * 16], HD);
            wmma::mma_sync(c[nt], a, b, c[nt]);
        }
        __syncthreads();
    }

    int node_local = lane >> 1;           // 0..15
    int halfsel = lane & 1;               // 0/1 -> dims +0 / +8
    int n = n0 + w * 16 + node_local;
    #pragma unroll
    for (int nt = 0; nt < 8; nt++) {
        wmma::store_matrix_sync(&sT[w][0][0], c[nt], 24, wmma::mem_row_major);
        __syncwarp();
        if (n < NN) {
            int hbase = nt * 16 + halfsel * 8;
            __align__(16) __half hb[8];
            #pragma unroll
            for (int j = 0; j < 8; j++) {
                float v = sT[w][node_local][halfsel * 8 + j] + g_bc[hbase + j];
                hb[j] = __float2half_rn(v);
            }
            uint4 pk = *reinterpret_cast<uint4*>(hb);
            *reinterpret_cast<uint4*>(&g_u0[(size_t)n * HD + hbase]) = pk;
            *reinterpret_cast<uint4*>(&g_hh[(size_t)n * HD + hbase]) = pk;
        }
        __syncwarp();
    }
}

// ---------------------------------------------------------------------------
// In-degree histogram over dst (int4-vectorized; EE % 4 == 0)
// ---------------------------------------------------------------------------
__global__ void hist_k(const int* __restrict__ ei) {
    int t = blockIdx.x * blockDim.x + threadIdx.x;
    int e = t * 4;
    if (e < EE) {
        int4 d = *reinterpret_cast<const int4*>(ei + EE + e);
        atomicAdd(&g_cnt[d.x], 1);
        atomicAdd(&g_cnt[d.y], 1);
        atomicAdd(&g_cnt[d.z], 1);
        atomicAdd(&g_cnt[d.w], 1);
    }
}

// ---------------------------------------------------------------------------
// ONE-launch exclusive scan: block b redundantly sums counts [0, b*1024)
// (coalesced, parallel), then warp-scans its own chunk. No spills.
// ---------------------------------------------------------------------------
__device__ __forceinline__ int warp_iscan(int v, int lane) {
    #pragma unroll
    for (int off = 1; off < 32; off <<= 1) {
        int u = __shfl_up_sync(0xffffffffu, v, off);
        if (lane >= off) v += u;
    }
    return v;
}

__global__ __launch_bounds__(SCAN_B) void scan_k() {
    __shared__ int wsum[32];
    __shared__ int sboff;
    int t = threadIdx.x, lane = t & 31, wid = t >> 5;

    int limit = blockIdx.x * SCAN_B;
    int acc = 0;
    for (int i = t; i < limit; i += SCAN_B) acc += g_cnt[i];
    #pragma unroll
    for (int off = 16; off > 0; off >>= 1)
        acc += __shfl_down_sync(0xffffffffu, acc, off);
    if (lane == 0) wsum[wid] = acc;
    __syncthreads();
    if (wid == 0) {
        int v = wsum[lane];
        #pragma unroll
        for (int off = 16; off > 0; off >>= 1)
            v += __shfl_down_sync(0xffffffffu, v, off);
        if (lane == 0) sboff = v;
    }
    __syncthreads();
    int boff = sboff;

    int idx = blockIdx.x * SCAN_B + t;
    int c = (idx < NN) ? g_cnt[idx] : 0;
    int v = warp_iscan(c, lane);
    if (lane == 31) wsum[wid] = v;
    __syncthreads();
    if (wid == 0) wsum[lane] = warp_iscan(wsum[lane], lane);
    __syncthreads();
    int incl = v + (wid ? wsum[wid - 1] : 0) + boff;
    if (idx < NN) {
        g_rowptr[idx + 1] = incl;
        g_wptr[idx]       = incl - c;
    }
    if (idx == 0) g_rowptr[0] = 0;
}

// ---------------------------------------------------------------------------
// Scatter edges into CSR order (by dst); 4 edges/thread, vectorized reads
// ---------------------------------------------------------------------------
__global__ void scatter_k(const int* __restrict__ ei, const float* __restrict__ ew) {
    int t = blockIdx.x * blockDim.x + threadIdx.x;
    int e = t * 4;
    if (e < EE) {
        int4  s4 = *reinterpret_cast<const int4*>(ei + e);
        int4  d4 = *reinterpret_cast<const int4*>(ei + EE + e);
        float4 w4 = *reinterpret_cast<const float4*>(ew + e);
        int p;
        p = atomicAdd(&g_wptr[d4.x], 1);
        g_edges[p] = ((unsigned int)__half_as_ushort(__float2half_rn(w4.x)) << 16) | (unsigned int)(s4.x & 0xFFFF);
        p = atomicAdd(&g_wptr[d4.y], 1);
        g_edges[p] = ((unsigned int)__half_as_ushort(__float2half_rn(w4.y)) << 16) | (unsigned int)(s4.y & 0xFFFF);
        p = atomicAdd(&g_wptr[d4.z], 1);
        g_edges[p] = ((unsigned int)__half_as_ushort(__float2half_rn(w4.z)) << 16) | (unsigned int)(s4.z & 0xFFFF);
        p = atomicAdd(&g_wptr[d4.w], 1);
        g_edges[p] = ((unsigned int)__half_as_ushort(__float2half_rn(w4.w)) << 16) | (unsigned int)(s4.w & 0xFFFF);
    }
}

// ---------------------------------------------------------------------------
// One scaled APPNP step (R6 form — best measured):
//   u_out[d] = (0.9/16) * sum_e w_e * u_in[src_e] + (0.1/16^{k+1}) * h[d]
// HALF-WARP per dst node; 4-edge unrolled mainloop.
// ---------------------------------------------------------------------------
__device__ __forceinline__ void edge_fma(unsigned int rec,
                                         const uint4* __restrict__ xin, int sub,
                                         float2& a0, float2& a1, float2& a2, float2& a3) {
    int src = (int)(rec & 0xFFFFu);
    float w = __half2float(__ushort_as_half((unsigned short)(rec >> 16)));
    uint4 raw = xin[src * 16 + sub];
    float2 p0 = __half22float2(*reinterpret_cast<const __half2*>(&raw.x));
    float2 p1 = __half22float2(*reinterpret_cast<const __half2*>(&raw.y));
    float2 p2 = __half22float2(*reinterpret_cast<const __half2*>(&raw.z));
    float2 p3 = __half22float2(*reinterpret_cast<const __half2*>(&raw.w));
    a0.x = fmaf(w, p0.x, a0.x); a0.y = fmaf(w, p0.y, a0.y);
    a1.x = fmaf(w, p1.x, a1.x); a1.y = fmaf(w, p1.y, a1.y);
    a2.x = fmaf(w, p2.x, a2.x); a2.y = fmaf(w, p2.y, a2.y);
    a3.x = fmaf(w, p3.x, a3.x); a3.y = fmaf(w, p3.y, a3.y);
}

__global__ __launch_bounds__(256) void prop_k(int flip, float coefH) {
    const uint4* __restrict__ xin =
        reinterpret_cast<const uint4*>(flip ? g_u1 : g_u0);
    uint4* __restrict__ xout =
        reinterpret_cast<uint4*>(flip ? g_u0 : g_u1);
    int node = (blockIdx.x * blockDim.x + threadIdx.x) >> 4;  // half-warp id
    int sub = threadIdx.x & 15;
    if (node >= NN) return;
    int beg = g_rowptr[node];
    int end = g_rowptr[node + 1];
    float2 a0 = make_float2(0.f, 0.f), a1 = a0, a2 = a0, a3 = a0;

    int j = beg;
    for (; j + 4 <= end; j += 4) {
        unsigned int r0 = g_edges[j + 0];
        unsigned int r1 = g_edges[j + 1];
        unsigned int r2 = g_edges[j + 2];
        unsigned int r3 = g_edges[j + 3];
        int s0 = (int)(r0 & 0xFFFFu), s1 = (int)(r1 & 0xFFFFu);
        int s2 = (int)(r2 & 0xFFFFu), s3 = (int)(r3 & 0xFFFFu);
        uint4 q0 = xin[s0 * 16 + sub];
        uint4 q1 = xin[s1 * 16 + sub];
        uint4 q2 = xin[s2 * 16 + sub];
        uint4 q3 = xin[s3 * 16 + sub];
        float w0 = __half2float(__ushort_as_half((unsigned short)(r0 >> 16)));
        float w1 = __half2float(__ushort_as_half((unsigned short)(r1 >> 16)));
        float w2 = __half2float(__ushort_as_half((unsigned short)(r2 >> 16)));
        float w3 = __half2float(__ushort_as_half((unsigned short)(r3 >> 16)));
        {
            float2 p0 = __half22float2(*reinterpret_cast<const __half2*>(&q0.x));
            float2 p1 = __half22float2(*reinterpret_cast<const __half2*>(&q0.y));
            float2 p2 = __half22float2(*reinterpret_cast<const __half2*>(&q0.z));
            float2 p3 = __half22float2(*reinterpret_cast<const __half2*>(&q0.w));
            a0.x = fmaf(w0, p0.x, a0.x); a0.y = fmaf(w0, p0.y, a0.y);
            a1.x = fmaf(w0, p1.x, a1.x); a1.y = fmaf(w0, p1.y, a1.y);
            a2.x = fmaf(w0, p2.x, a2.x); a2.y = fmaf(w0, p2.y, a2.y);
            a3.x = fmaf(w0, p3.x, a3.x); a3.y = fmaf(w0, p3.y, a3.y);
        }
        {
            float2 p0 = __half22float2(*reinterpret_cast<const __half2*>(&q1.x));
            float2 p1 = __half22float2(*reinterpret_cast<const __half2*>(&q1.y));
            float2 p2 = __half22float2(*reinterpret_cast<const __half2*>(&q1.z));
            float2 p3 = __half22float2(*reinterpret_cast<const __half2*>(&q1.w));
            a0.x = fmaf(w1, p0.x, a0.x); a0.y = fmaf(w1, p0.y, a0.y);
            a1.x = fmaf(w1, p1.x, a1.x); a1.y = fmaf(w1, p1.y, a1.y);
            a2.x = fmaf(w1, p2.x, a2.x); a2.y = fmaf(w1, p2.y, a2.y);
            a3.x = fmaf(w1, p3.x, a3.x); a3.y = fmaf(w1, p3.y, a3.y);
        }
        {
            float2 p0 = __half22float2(*reinterpret_cast<const __half2*>(&q2.x));
            float2 p1 = __half22float2(*reinterpret_cast<const __half2*>(&q2.y));
            float2 p2 = __half22float2(*reinterpret_cast<const __half2*>(&q2.z));
            float2 p3 = __half22float2(*reinterpret_cast<const __half2*>(&q2.w));
            a0.x = fmaf(w2, p0.x, a0.x); a0.y = fmaf(w2, p0.y, a0.y);
            a1.x = fmaf(w2, p1.x, a1.x); a1.y = fmaf(w2, p1.y, a1.y);
            a2.x = fmaf(w2, p2.x, a2.x); a2.y = fmaf(w2, p2.y, a2.y);
            a3.x = fmaf(w2, p3.x, a3.x); a3.y = fmaf(w2, p3.y, a3.y);
        }
        {
            float2 p0 = __half22float2(*reinterpret_cast<const __half2*>(&q3.x));
            float2 p1 = __half22float2(*reinterpret_cast<const __half2*>(&q3.y));
            float2 p2 = __half22float2(*reinterpret_cast<const __half2*>(&q3.z));
            float2 p3 = __half22float2(*reinterpret_cast<const __half2*>(&q3.w));
            a0.x = fmaf(w3, p0.x, a0.x); a0.y = fmaf(w3, p0.y, a0.y);
            a1.x = fmaf(w3, p1.x, a1.x); a1.y = fmaf(w3, p1.y, a1.y);
            a2.x = fmaf(w3, p2.x, a2.x); a2.y = fmaf(w3, p2.y, a2.y);
            a3.x = fmaf(w3, p3.x, a3.x); a3.y = fmaf(w3, p3.y, a3.y);
        }
    }
    #pragma unroll 1
    for (; j < end; j++)
        edge_fma(g_edges[j], xin, sub, a0, a1, a2, a3);

    uint4 hraw = reinterpret_cast<const uint4*>(g_hh)[node * 16 + sub];
    float2 h0 = __half22float2(*reinterpret_cast<const __half2*>(&hraw.x));
    float2 h1 = __half22float2(*reinterpret_cast<const __half2*>(&hraw.y));
    float2 h2 = __half22float2(*reinterpret_cast<const __half2*>(&hraw.z));
    float2 h3 = __half22float2(*reinterpret_cast<const __half2*>(&hraw.w));
    float2 o0, o1, o2, o3;
    o0.x = fmaf(COEF_A, a0.x, coefH * h0.x); o0.y = fmaf(COEF_A, a0.y, coefH * h0.y);
    o1.x = fmaf(COEF_A, a1.x, coefH * h1.x); o1.y = fmaf(COEF_A, a1.y, coefH * h1.y);
    o2.x = fmaf(COEF_A, a2.x, coefH * h2.x); o2.y = fmaf(COEF_A, a2.y, coefH * h2.y);
    o3.x = fmaf(COEF_A, a3.x, coefH * h3.x); o3.y = fmaf(COEF_A, a3.y, coefH * h3.y);
    uint4 outw;
    *reinterpret_cast<__half2*>(&outw.x) = __float22half2_rn(o0);
    *reinterpret_cast<__half2*>(&outw.y) = __float22half2_rn(o1);
    *reinterpret_cast<__half2*>(&outw.z) = __float22half2_rn(o2);
    *reinterpret_cast<__half2*>(&outw.w) = __float22half2_rn(o3);
    xout[node * 16 + sub] = outw;
}

// ---------------------------------------------------------------------------
// Head WITH inline pooling: block g binary-searches its node range in sorted
// batch, sums final u rows directly (no atomics, no pool buffer), unscales,
// then y = relu(pool @ V0w + V0b) @ V1w + V1b; out = log_softmax(y).
// ---------------------------------------------------------------------------
__global__ __launch_bounds__(128) void head_pool_k(const int* __restrict__ batch,
                                                   const float* __restrict__ V0w,
                                                   const float* __restrict__ V0b,
                                                   const float* __restrict__ V1w,
                                                   const float* __restrict__ V1b,
                                                   float* __restrict__ out) {
    __shared__ float sp[HD];
    __shared__ float sz[HD];
    __shared__ float sy[OD];
    int g = blockIdx.x;
    int t = threadIdx.x;

    // lower_bound(batch, g) and lower_bound(batch, g+1), redundant per thread
    int lo = 0, hi = NN;
    while (lo < hi) { int mid = (lo + hi) >> 1; if (batch[mid] < g) lo = mid + 1; else hi = mid; }
    int s0 = lo;
    hi = NN;
    while (lo < hi) { int mid = (lo + hi) >> 1; if (batch[mid] < g + 1) lo = mid + 1; else hi = mid; }
    int s1 = lo;

    // pooled[t] = FINAL_SCALE * sum_n u0[n][t]  (coalesced: t spans the row)
    float acc = 0.f;
    for (int n = s0; n < s1; n++)
        acc += __half2float(g_u0[(size_t)n * HD + t]);
    sp[t] = acc * FINAL_SCALE;
    __syncthreads();

    float s = V0b[t];
    #pragma unroll 8
    for (int k = 0; k < HD; k++) s = fmaf(sp[k], V0w[k * HD + t], s);
    sz[t] = fmaxf(s, 0.f);
    __syncthreads();
    if (t < OD) {
        float y = V1b[t];
        #pragma unroll 8
        for (int h = 0; h < HD; h++) y = fmaf(sz[h], V1w[h * OD + t], y);
        sy[t] = y;
    }
    __syncthreads();
    if (t == 0) {
        float m = -INFINITY;
        #pragma unroll
        for (int o = 0; o < OD; o++) m = fmaxf(m, sy[o]);
        float sum = 0.f;
        #pragma unroll
        for (int o = 0; o < OD; o++) sum += expf(sy[o] - m);
        float lse = m + logf(sum);
        #pragma unroll
        for (int o = 0; o < OD; o++) out[g * OD + o] = sy[o] - lse;
    }
}

// ---------------------------------------------------------------------------
extern "C" void kernel_launch(void* const* d_in, const int* in_sizes, int n_in,
                              void* d_out, int out_size) {
    const float* features    = (const float*)d_in[0];
    const float* edge_weight = (const float*)d_in[1];
    const float* W1  = (const float*)d_in[2];
    const float* b1  = (const float*)d_in[3];
    const float* W2  = (const float*)d_in[4];
    const float* b2  = (const float*)d_in[5];
    const float* V0w = (const float*)d_in[6];
    const float* V0b = (const float*)d_in[7];
    const float* V1w = (const float*)d_in[8];
    const float* V1b = (const float*)d_in[9];
    const int* edge_index = (const int*)d_in[10];
    const int* batch      = (const int*)d_in[11];
    float* out = (float*)d_out;

    // MLP-weight fusion + cnt zeroing, then wmma node GEMM
    int zero_blocks = (NN + 127) / 128;
    fuse_zero_k<<<HD + 1 + zero_blocks, HD>>>(W1, b1, W2, b2);
    gemm_x0_wmma_k<<<(NN + 127) / 128, 256>>>(features);

    // CSR build (by dst) — hist, one-launch scan, scatter
    hist_k<<<(EE / 4 + 255) / 256, 256>>>(edge_index);
    scan_k<<<SCAN_NBLK, SCAN_B>>>();
    scatter_k<<<(EE / 4 + 255) / 256, 256>>>(edge_index, edge_weight);

    // APPNP propagation, K=10 (scaled fp16; ends in g_u0)
    int prop_blocks = (NN * 16 + 255) / 256;
    float cscale = 1.0f;   // 1/16^{it}
    for (int it = 0; it < KIT; it++) {
        cscale *= 0.0625f;                    // 1/16^{it+1}
        float coefH = ALPHA_F * cscale;
        prop_k<<<prop_blocks, 256>>>(it & 1, coefH);
    }

    // Fused pool + head (one launch, no atomics)
    head_pool_k<<<GG, HD>>>(batch, V0w, V0b, V1w, V1b, out);
}

// round 15
// speedup vs baseline: 1.2239x; 1.0656x over previous
#include <cuda_runtime.h>
#include <cuda_fp16.h>
#include <mma.h>
#include <math.h>

using namespace nvcuda;

#define NN 50000
#define EE 1600000
#define HD 128
#define GG 512
#define OD 10
#define KIT 10
#define ALPHA_F 0.1f
#define COEF_A (0.9f / 16.0f)        // per-step rescale by 16
#define FINAL_SCALE 1099511627776.0f // 16^10 = 2^40 (exact)

#define SCAN_B 1024
#define SCAN_NBLK ((NN + SCAN_B - 1) / SCAN_B)   // 49

// -------- device scratch (no allocations allowed) --------
__device__ __half g_u0[(size_t)NN * HD];   // ping (scaled x)
__device__ __half g_u1[(size_t)NN * HD];   // pong
__device__ __half g_hh[(size_t)NN * HD];   // teleport term (fp16)
__device__ __half g_Wc16[HD * HD];         // fused W1@W2 (fp16 for wmma)
__device__ float  g_bc[HD];                // fused b1@W2 + b2
__device__ int    g_cnt[NN];               // in-degree histogram
__device__ int    g_rowptr[NN + 1];        // CSR row pointers (by dst)
__device__ int    g_wptr[NN];              // scatter write cursors
__device__ unsigned int g_edges[EE];       // packed: (half w)<<16 | u16 src

// ---------------------------------------------------------------------------
// Fuse the two linear layers (Wc16 = fp16(W1@W2), bc = b1@W2 + b2) AND zero
// the histogram.
// ---------------------------------------------------------------------------
__global__ void fuse_zero_k(const float* __restrict__ W1, const float* __restrict__ b1,
                            const float* __restrict__ W2, const float* __restrict__ b2) {
    int h = threadIdx.x;
    if (blockIdx.x < HD) {
        int k = blockIdx.x;
        float s = 0.f;
        #pragma unroll 8
        for (int j = 0; j < HD; j++) s = fmaf(W1[k * HD + j], W2[j * HD + h], s);
        g_Wc16[k * HD + h] = __float2half_rn(s);
    } else if (blockIdx.x == HD) {
        float s = b2[h];
        #pragma unroll 8
        for (int j = 0; j < HD; j++) s = fmaf(b1[j], W2[j * HD + h], s);
        g_bc[h] = s;
    } else {
        int i = (blockIdx.x - HD - 1) * 128 + h;
        if (i < NN) g_cnt[i] = 0;
    }
}

// ---------------------------------------------------------------------------
// x0 = F^T @ Wc + bc via wmma (fp16 in, fp32 accum). Writes g_u0 & g_hh.
// ---------------------------------------------------------------------------
__global__ __launch_bounds__(256) void gemm_x0_wmma_k(const float* __restrict__ F) {
    __shared__ __half sA[16][128];        // F tile (k rows x 128 nodes), fp16
    __shared__ float  sT[8][16][24];      // per-warp epilogue staging
    int n0 = blockIdx.x * 128;
    int tid = threadIdx.x;
    int w = tid >> 5;
    int lane = tid & 31;

    wmma::fragment<wmma::accumulator, 16, 16, 16, float> c[8];
    #pragma unroll
    for (int nt = 0; nt < 8; nt++) wmma::fill_fragment(c[nt], 0.f);

    for (int ks = 0; ks < 8; ks++) {
        #pragma unroll
        for (int i = tid; i < 16 * 128; i += 256) {
            int kk = i >> 7, cc = i & 127;
            int n = n0 + cc;
            float v = (n < NN) ? F[(size_t)(ks * 16 + kk) * NN + n] : 0.f;
            sA[kk][cc] = __float2half_rn(v);
        }
        __syncthreads();
        wmma::fragment<wmma::matrix_a, 16, 16, 16, __half, wmma::col_major> a;
        wmma::load_matrix_sync(a, &sA[0][w * 16], 128);
        #pragma unroll
        for (int nt = 0; nt < 8; nt++) {
            wmma::fragment<wmma::matrix_b, 16, 16, 16, __half, wmma::row_major> b;
            wmma::load_matrix_sync(b, &g_Wc16[(ks * 16) * HD + nt * 16], HD);
            wmma::mma_sync(c[nt], a, b, c[nt]);
        }
        __syncthreads();
    }

    int node_local = lane >> 1;           // 0..15
    int halfsel = lane & 1;               // 0/1 -> dims +0 / +8
    int n = n0 + w * 16 + node_local;
    #pragma unroll
    for (int nt = 0; nt < 8; nt++) {
        wmma::store_matrix_sync(&sT[w][0][0], c[nt], 24, wmma::mem_row_major);
        __syncwarp();
        if (n < NN) {
            int hbase = nt * 16 + halfsel * 8;
            __align__(16) __half hb[8];
            #pragma unroll
            for (int j = 0; j < 8; j++) {
                float v = sT[w][node_local][halfsel * 8 + j] + g_bc[hbase + j];
                hb[j] = __float2half_rn(v);
            }
            uint4 pk = *reinterpret_cast<uint4*>(hb);
            *reinterpret_cast<uint4*>(&g_u0[(size_t)n * HD + hbase]) = pk;
            *reinterpret_cast<uint4*>(&g_hh[(size_t)n * HD + hbase]) = pk;
        }
        __syncwarp();
    }
}

// ---------------------------------------------------------------------------
// In-degree histogram over dst (int4-vectorized; EE % 4 == 0)
// ---------------------------------------------------------------------------
__global__ void hist_k(const int* __restrict__ ei) {
    int t = blockIdx.x * blockDim.x + threadIdx.x;
    int e = t * 4;
    if (e < EE) {
        int4 d = *reinterpret_cast<const int4*>(ei + EE + e);
        atomicAdd(&g_cnt[d.x], 1);
        atomicAdd(&g_cnt[d.y], 1);
        atomicAdd(&g_cnt[d.z], 1);
        atomicAdd(&g_cnt[d.w], 1);
    }
}

// ---------------------------------------------------------------------------
// ONE-launch exclusive scan: block b redundantly sums counts [0, b*1024)
// (coalesced, parallel), then warp-scans its own chunk. No spills.
// ---------------------------------------------------------------------------
__device__ __forceinline__ int warp_iscan(int v, int lane) {
    #pragma unroll
    for (int off = 1; off < 32; off <<= 1) {
        int u = __shfl_up_sync(0xffffffffu, v, off);
        if (lane >= off) v += u;
    }
    return v;
}

__global__ __launch_bounds__(SCAN_B) void scan_k() {
    __shared__ int wsum[32];
    __shared__ int sboff;
    int t = threadIdx.x, lane = t & 31, wid = t >> 5;

    int limit = blockIdx.x * SCAN_B;
    int acc = 0;
    for (int i = t; i < limit; i += SCAN_B) acc += g_cnt[i];
    #pragma unroll
    for (int off = 16; off > 0; off >>= 1)
        acc += __shfl_down_sync(0xffffffffu, acc, off);
    if (lane == 0) wsum[wid] = acc;
    __syncthreads();
    if (wid == 0) {
        int v = wsum[lane];
        #pragma unroll
        for (int off = 16; off > 0; off >>= 1)
            v += __shfl_down_sync(0xffffffffu, v, off);
        if (lane == 0) sboff = v;
    }
    __syncthreads();
    int boff = sboff;

    int idx = blockIdx.x * SCAN_B + t;
    int c = (idx < NN) ? g_cnt[idx] : 0;
    int v = warp_iscan(c, lane);
    if (lane == 31) wsum[wid] = v;
    __syncthreads();
    if (wid == 0) wsum[lane] = warp_iscan(wsum[lane], lane);
    __syncthreads();
    int incl = v + (wid ? wsum[wid - 1] : 0) + boff;
    if (idx < NN) {
        g_rowptr[idx + 1] = incl;
        g_wptr[idx]       = incl - c;
    }
    if (idx == 0) g_rowptr[0] = 0;
}

// ---------------------------------------------------------------------------
// Scatter edges into CSR order (by dst); 4 edges/thread, vectorized reads
// ---------------------------------------------------------------------------
__global__ void scatter_k(const int* __restrict__ ei, const float* __restrict__ ew) {
    int t = blockIdx.x * blockDim.x + threadIdx.x;
    int e = t * 4;
    if (e < EE) {
        int4  s4 = *reinterpret_cast<const int4*>(ei + e);
        int4  d4 = *reinterpret_cast<const int4*>(ei + EE + e);
        float4 w4 = *reinterpret_cast<const float4*>(ew + e);
        int p;
        p = atomicAdd(&g_wptr[d4.x], 1);
        g_edges[p] = ((unsigned int)__half_as_ushort(__float2half_rn(w4.x)) << 16) | (unsigned int)(s4.x & 0xFFFF);
        p = atomicAdd(&g_wptr[d4.y], 1);
        g_edges[p] = ((unsigned int)__half_as_ushort(__float2half_rn(w4.y)) << 16) | (unsigned int)(s4.y & 0xFFFF);
        p = atomicAdd(&g_wptr[d4.z], 1);
        g_edges[p] = ((unsigned int)__half_as_ushort(__float2half_rn(w4.z)) << 16) | (unsigned int)(s4.z & 0xFFFF);
        p = atomicAdd(&g_wptr[d4.w], 1);
        g_edges[p] = ((unsigned int)__half_as_ushort(__float2half_rn(w4.w)) << 16) | (unsigned int)(s4.w & 0xFFFF);
    }
}

// ---------------------------------------------------------------------------
// One scaled APPNP step (R6 form — best measured):
//   u_out[d] = (0.9/16) * sum_e w_e * u_in[src_e] + (0.1/16^{k+1}) * h[d]
// HALF-WARP per dst node; 4-edge unrolled mainloop.
// ---------------------------------------------------------------------------
__device__ __forceinline__ void edge_fma(unsigned int rec,
                                         const uint4* __restrict__ xin, int sub,
                                         float2& a0, float2& a1, float2& a2, float2& a3) {
    int src = (int)(rec & 0xFFFFu);
    float w = __half2float(__ushort_as_half((unsigned short)(rec >> 16)));
    uint4 raw = xin[src * 16 + sub];
    float2 p0 = __half22float2(*reinterpret_cast<const __half2*>(&raw.x));
    float2 p1 = __half22float2(*reinterpret_cast<const __half2*>(&raw.y));
    float2 p2 = __half22float2(*reinterpret_cast<const __half2*>(&raw.z));
    float2 p3 = __half22float2(*reinterpret_cast<const __half2*>(&raw.w));
    a0.x = fmaf(w, p0.x, a0.x); a0.y = fmaf(w, p0.y, a0.y);
    a1.x = fmaf(w, p1.x, a1.x); a1.y = fmaf(w, p1.y, a1.y);
    a2.x = fmaf(w, p2.x, a2.x); a2.y = fmaf(w, p2.y, a2.y);
    a3.x = fmaf(w, p3.x, a3.x); a3.y = fmaf(w, p3.y, a3.y);
}

__global__ __launch_bounds__(256) void prop_k(int flip, float coefH) {
    const uint4* __restrict__ xin =
        reinterpret_cast<const uint4*>(flip ? g_u1 : g_u0);
    uint4* __restrict__ xout =
        reinterpret_cast<uint4*>(flip ? g_u0 : g_u1);
    int node = (blockIdx.x * blockDim.x + threadIdx.x) >> 4;  // half-warp id
    int sub = threadIdx.x & 15;
    if (node >= NN) return;
    int beg = g_rowptr[node];
    int end = g_rowptr[node + 1];
    float2 a0 = make_float2(0.f, 0.f), a1 = a0, a2 = a0, a3 = a0;

    int j = beg;
    for (; j + 4 <= end; j += 4) {
        unsigned int r0 = g_edges[j + 0];
        unsigned int r1 = g_edges[j + 1];
        unsigned int r2 = g_edges[j + 2];
        unsigned int r3 = g_edges[j + 3];
        int s0 = (int)(r0 & 0xFFFFu), s1 = (int)(r1 & 0xFFFFu);
        int s2 = (int)(r2 & 0xFFFFu), s3 = (int)(r3 & 0xFFFFu);
        uint4 q0 = xin[s0 * 16 + sub];
        uint4 q1 = xin[s1 * 16 + sub];
        uint4 q2 = xin[s2 * 16 + sub];
        uint4 q3 = xin[s3 * 16 + sub];
        float w0 = __half2float(__ushort_as_half((unsigned short)(r0 >> 16)));
        float w1 = __half2float(__ushort_as_half((unsigned short)(r1 >> 16)));
        float w2 = __half2float(__ushort_as_half((unsigned short)(r2 >> 16)));
        float w3 = __half2float(__ushort_as_half((unsigned short)(r3 >> 16)));
        {
            float2 p0 = __half22float2(*reinterpret_cast<const __half2*>(&q0.x));
            float2 p1 = __half22float2(*reinterpret_cast<const __half2*>(&q0.y));
            float2 p2 = __half22float2(*reinterpret_cast<const __half2*>(&q0.z));
            float2 p3 = __half22float2(*reinterpret_cast<const __half2*>(&q0.w));
            a0.x = fmaf(w0, p0.x, a0.x); a0.y = fmaf(w0, p0.y, a0.y);
            a1.x = fmaf(w0, p1.x, a1.x); a1.y = fmaf(w0, p1.y, a1.y);
            a2.x = fmaf(w0, p2.x, a2.x); a2.y = fmaf(w0, p2.y, a2.y);
            a3.x = fmaf(w0, p3.x, a3.x); a3.y = fmaf(w0, p3.y, a3.y);
        }
        {
            float2 p0 = __half22float2(*reinterpret_cast<const __half2*>(&q1.x));
            float2 p1 = __half22float2(*reinterpret_cast<const __half2*>(&q1.y));
            float2 p2 = __half22float2(*reinterpret_cast<const __half2*>(&q1.z));
            float2 p3 = __half22float2(*reinterpret_cast<const __half2*>(&q1.w));
            a0.x = fmaf(w1, p0.x, a0.x); a0.y = fmaf(w1, p0.y, a0.y);
            a1.x = fmaf(w1, p1.x, a1.x); a1.y = fmaf(w1, p1.y, a1.y);
            a2.x = fmaf(w1, p2.x, a2.x); a2.y = fmaf(w1, p2.y, a2.y);
            a3.x = fmaf(w1, p3.x, a3.x); a3.y = fmaf(w1, p3.y, a3.y);
        }
        {
            float2 p0 = __half22float2(*reinterpret_cast<const __half2*>(&q2.x));
            float2 p1 = __half22float2(*reinterpret_cast<const __half2*>(&q2.y));
            float2 p2 = __half22float2(*reinterpret_cast<const __half2*>(&q2.z));
            float2 p3 = __half22float2(*reinterpret_cast<const __half2*>(&q2.w));
            a0.x = fmaf(w2, p0.x, a0.x); a0.y = fmaf(w2, p0.y, a0.y);
            a1.x = fmaf(w2, p1.x, a1.x); a1.y = fmaf(w2, p1.y, a1.y);
            a2.x = fmaf(w2, p2.x, a2.x); a2.y = fmaf(w2, p2.y, a2.y);
            a3.x = fmaf(w2, p3.x, a3.x); a3.y = fmaf(w2, p3.y, a3.y);
        }
        {
            float2 p0 = __half22float2(*reinterpret_cast<const __half2*>(&q3.x));
            float2 p1 = __half22float2(*reinterpret_cast<const __half2*>(&q3.y));
            float2 p2 = __half22float2(*reinterpret_cast<const __half2*>(&q3.z));
            float2 p3 = __half22float2(*reinterpret_cast<const __half2*>(&q3.w));
            a0.x = fmaf(w3, p0.x, a0.x); a0.y = fmaf(w3, p0.y, a0.y);
            a1.x = fmaf(w3, p1.x, a1.x); a1.y = fmaf(w3, p1.y, a1.y);
            a2.x = fmaf(w3, p2.x, a2.x); a2.y = fmaf(w3, p2.y, a2.y);
            a3.x = fmaf(w3, p3.x, a3.x); a3.y = fmaf(w3, p3.y, a3.y);
        }
    }
    #pragma unroll 1
    for (; j < end; j++)
        edge_fma(g_edges[j], xin, sub, a0, a1, a2, a3);

    uint4 hraw = reinterpret_cast<const uint4*>(g_hh)[node * 16 + sub];
    float2 h0 = __half22float2(*reinterpret_cast<const __half2*>(&hraw.x));
    float2 h1 = __half22float2(*reinterpret_cast<const __half2*>(&hraw.y));
    float2 h2 = __half22float2(*reinterpret_cast<const __half2*>(&hraw.z));
    float2 h3 = __half22float2(*reinterpret_cast<const __half2*>(&hraw.w));
    float2 o0, o1, o2, o3;
    o0.x = fmaf(COEF_A, a0.x, coefH * h0.x); o0.y = fmaf(COEF_A, a0.y, coefH * h0.y);
    o1.x = fmaf(COEF_A, a1.x, coefH * h1.x); o1.y = fmaf(COEF_A, a1.y, coefH * h1.y);
    o2.x = fmaf(COEF_A, a2.x, coefH * h2.x); o2.y = fmaf(COEF_A, a2.y, coefH * h2.y);
    o3.x = fmaf(COEF_A, a3.x, coefH * h3.x); o3.y = fmaf(COEF_A, a3.y, coefH * h3.y);
    uint4 outw;
    *reinterpret_cast<__half2*>(&outw.x) = __float22half2_rn(o0);
    *reinterpret_cast<__half2*>(&outw.y) = __float22half2_rn(o1);
    *reinterpret_cast<__half2*>(&outw.z) = __float22half2_rn(o2);
    *reinterpret_cast<__half2*>(&outw.w) = __float22half2_rn(o3);
    xout[node * 16 + sub] = outw;
}

// ---------------------------------------------------------------------------
// Head WITH inline pooling: block g binary-searches its node range in sorted
// batch, sums final u rows directly, unscales, then MLP head + log_softmax.
// ---------------------------------------------------------------------------
__global__ __launch_bounds__(128) void head_pool_k(const int* __restrict__ batch,
                                                   const float* __restrict__ V0w,
                                                   const float* __restrict__ V0b,
                                                   const float* __restrict__ V1w,
                                                   const float* __restrict__ V1b,
                                                   float* __restrict__ out) {
    __shared__ float sp[HD];
    __shared__ float sz[HD];
    __shared__ float sy[OD];
    int g = blockIdx.x;
    int t = threadIdx.x;

    int lo = 0, hi = NN;
    while (lo < hi) { int mid = (lo + hi) >> 1; if (batch[mid] < g) lo = mid + 1; else hi = mid; }
    int s0 = lo;
    hi = NN;
    while (lo < hi) { int mid = (lo + hi) >> 1; if (batch[mid] < g + 1) lo = mid + 1; else hi = mid; }
    int s1 = lo;

    float acc = 0.f;
    for (int n = s0; n < s1; n++)
        acc += __half2float(g_u0[(size_t)n * HD + t]);
    sp[t] = acc * FINAL_SCALE;
    __syncthreads();

    float s = V0b[t];
    #pragma unroll 8
    for (int k = 0; k < HD; k++) s = fmaf(sp[k], V0w[k * HD + t], s);
    sz[t] = fmaxf(s, 0.f);
    __syncthreads();
    if (t < OD) {
        float y = V1b[t];
        #pragma unroll 8
        for (int h = 0; h < HD; h++) y = fmaf(sz[h], V1w[h * OD + t], y);
        sy[t] = y;
    }
    __syncthreads();
    if (t == 0) {
        float m = -INFINITY;
        #pragma unroll
        for (int o = 0; o < OD; o++) m = fmaxf(m, sy[o]);
        float sum = 0.f;
        #pragma unroll
        for (int o = 0; o < OD; o++) sum += expf(sy[o] - m);
        float lse = m + logf(sum);
        #pragma unroll
        for (int o = 0; o < OD; o++) out[g * OD + o] = sy[o] - lse;
    }
}

// ---------------------------------------------------------------------------
extern "C" void kernel_launch(void* const* d_in, const int* in_sizes, int n_in,
                              void* d_out, int out_size) {
    const float* features    = (const float*)d_in[0];
    const float* edge_weight = (const float*)d_in[1];
    const float* W1  = (const float*)d_in[2];
    const float* b1  = (const float*)d_in[3];
    const float* W2  = (const float*)d_in[4];
    const float* b2  = (const float*)d_in[5];
    const float* V0w = (const float*)d_in[6];
    const float* V0b = (const float*)d_in[7];
    const float* V1w = (const float*)d_in[8];
    const float* V1b = (const float*)d_in[9];
    const int* edge_index = (const int*)d_in[10];
    const int* batch      = (const int*)d_in[11];
    float* out = (float*)d_out;

    // One-time side stream + fork/join events (host objects, not device mem;
    // created on the first, uncaptured correctness call and reused so every
    // call — including the captured one — performs identical work).
    static cudaStream_t s2 = nullptr;
    static cudaEvent_t evFork = nullptr, evJoin = nullptr;
    if (s2 == nullptr) {
        cudaStreamCreateWithFlags(&s2, cudaStreamNonBlocking);
        cudaEventCreateWithFlags(&evFork, cudaEventDisableTiming);
        cudaEventCreateWithFlags(&evJoin, cudaEventDisableTiming);
    }

    // Stage 0: weight fusion + cnt zeroing (both branches depend on this)
    int zero_blocks = (NN + 127) / 128;
    fuse_zero_k<<<HD + 1 + zero_blocks, HD>>>(W1, b1, W2, b2);

    // Fork: CSR chain on s2, concurrent with the node GEMM on the main stream
    cudaEventRecord(evFork, 0);
    cudaStreamWaitEvent(s2, evFork, 0);

    hist_k<<<(EE / 4 + 255) / 256, 256, 0, s2>>>(edge_index);
    scan_k<<<SCAN_NBLK, SCAN_B, 0, s2>>>();
    scatter_k<<<(EE / 4 + 255) / 256, 256, 0, s2>>>(edge_index, edge_weight);
    cudaEventRecord(evJoin, s2);

    gemm_x0_wmma_k<<<(NN + 127) / 128, 256>>>(features);

    // Join: prop needs both the CSR (s2) and u0/hh (main)
    cudaStreamWaitEvent(0, evJoin, 0);

    // APPNP propagation, K=10 (scaled fp16; ends in g_u0)
    int prop_blocks = (NN * 16 + 255) / 256;
    float cscale = 1.0f;   // 1/16^{it}
    for (int it = 0; it < KIT; it++) {
        cscale *= 0.0625f;                    // 1/16^{it+1}
        float coefH = ALPHA_F * cscale;
        prop_k<<<prop_blocks, 256>>>(it & 1, coefH);
    }

    // Fused pool + head (one launch, no atomics)
    head_pool_k<<<GG, HD>>>(batch, V0w, V0b, V1w, V1b, out);
}